// round 2
// baseline (speedup 1.0000x reference)
#include <cuda_runtime.h>

// FeatNeighbourCorr: out[b,k,h,w] = <n(p), n(q_k)>, n = feats / ||feats||_C,
// q_k = p - d_k, d = (1,0)(1,1)(0,1)(-1,1)(-1,0)(-1,-1)(0,-1)(1,-1), reflect pad.
// R2: f32x2 channel-pair math (FFMA2 + LDS.64) + cp.async double-buffered pipeline.

#define HH 256
#define WW 256
#define CC 128
#define HW (HH * WW)
#define TH 16
#define TW 32
#define KC 8                  // channels per chunk
#define NPAIR (KC / 2)
#define NCHUNK (CC / KC)      // 16
#define SROWS (TH + 2)        // 18
#define SCOLS (TW + 2)        // 34
#define SSTR 35               // padded row stride, float2 units
#define NPIX (SROWS * SCOLS)  // 612
#define NTHREADS 256
#define PLANE (SROWS * SSTR)  // float2 per pair-plane
#define NSLOT 3               // ceil(612/256)

typedef unsigned long long u64;

__device__ __forceinline__ void fma2(u64& d, u64 a, u64 b) {
    asm("fma.rn.f32x2 %0, %1, %2, %0;" : "+l"(d) : "l"(a), "l"(b));
}
__device__ __forceinline__ float sum2(u64 a) {
    return __uint_as_float((unsigned)a) + __uint_as_float((unsigned)(a >> 32));
}

__global__ __launch_bounds__(NTHREADS, 3)
void featcorr_kernel(const float* __restrict__ feats, float* __restrict__ out) {
    __shared__ u64 sbuf[2][NPAIR * PLANE];   // 2 x 4 x 630 x 8B = 40320 B
    __shared__ float srn[NPIX];              // 2448 B

    const int t  = threadIdx.x;
    const int b  = blockIdx.z;
    const int h0 = blockIdx.y * TH;
    const int w0 = blockIdx.x * TW;

    // ---- per-thread load slots over the 34x18 staged tile (chunk-invariant) ----
    int  goff[NSLOT], soff[NSLOT];
    bool valid[NSLOT];
#pragma unroll
    for (int u = 0; u < NSLOT; ++u) {
        int i = t + u * NTHREADS;
        valid[u] = (i < NPIX);
        int ii = valid[u] ? i : 0;
        int yy = ii / SCOLS, xx = ii - yy * SCOLS;
        int gh = h0 + yy - 1; gh = gh < 0 ? -gh : (gh >= HH ? 2 * HH - 2 - gh : gh);
        int gw = w0 + xx - 1; gw = gw < 0 ? -gw : (gw >= WW ? 2 * WW - 2 - gw : gw);
        goff[u] = gh * WW + gw;
        soff[u] = yy * SSTR + xx;            // float2-unit pixel index
    }

    const float* fb = feats + (size_t)b * CC * HW;

    // ---- async-stage one 8-channel chunk into buffer bs (4B elements) ----
    auto issue = [&](int ch, int bs) {
        const float* fc = fb + (size_t)ch * KC * HW;
#pragma unroll
        for (int u = 0; u < NSLOT; ++u) {
            if (valid[u]) {
                unsigned dbase = (unsigned)__cvta_generic_to_shared(sbuf[bs])
                               + (unsigned)(soff[u] * 8);
                const float* src = fc + goff[u];
#pragma unroll
                for (int c = 0; c < KC; ++c) {
                    unsigned da = dbase + (unsigned)((c >> 1) * (PLANE * 8) + (c & 1) * 4);
                    asm volatile("cp.async.ca.shared.global [%0], [%1], 4;"
                                 :: "r"(da), "l"(src + c * HW) : "memory");
                }
            }
        }
        asm volatile("cp.async.commit_group;" ::: "memory");
    };

    // thread -> 1x2 output strip: row py, cols px0, px0+1
    const int py  = t >> 4;
    const int px0 = (t & 15) << 1;

    u64 acc[2][8];
#pragma unroll
    for (int i = 0; i < 2; ++i)
#pragma unroll
        for (int k = 0; k < 8; ++k) acc[i][k] = 0ull;
    u64 ssacc[NSLOT];
#pragma unroll
    for (int u = 0; u < NSLOT; ++u) ssacc[u] = 0ull;

    issue(0, 0);
    for (int ch = 0; ch < NCHUNK; ++ch) {
        if (ch + 1 < NCHUNK) {
            issue(ch + 1, (ch + 1) & 1);
            asm volatile("cp.async.wait_group 1;" ::: "memory");
        } else {
            asm volatile("cp.async.wait_group 0;" ::: "memory");
        }
        __syncthreads();

        const int bs = ch & 1;
#pragma unroll
        for (int p = 0; p < NPAIR; ++p) {
            const u64* pl = sbuf[bs] + p * PLANE;
            const int base = py * SSTR + px0;
            u64 tr[4], mr[4], br[4];
#pragma unroll
            for (int j = 0; j < 4; ++j) {
                tr[j] = pl[base + j];
                mr[j] = pl[base + SSTR + j];
                br[j] = pl[base + 2 * SSTR + j];
            }
#pragma unroll
            for (int i = 0; i < 2; ++i) {
                u64 cv = mr[i + 1];
                fma2(acc[i][0], cv, tr[i + 1]);  // ( 1, 0)
                fma2(acc[i][1], cv, tr[i]);      // ( 1, 1)
                fma2(acc[i][2], cv, mr[i]);      // ( 0, 1)
                fma2(acc[i][3], cv, br[i]);      // (-1, 1)
                fma2(acc[i][4], cv, br[i + 1]);  // (-1, 0)
                fma2(acc[i][5], cv, br[i + 2]);  // (-1,-1)
                fma2(acc[i][6], cv, mr[i + 2]);  // ( 0,-1)
                fma2(acc[i][7], cv, tr[i + 2]);  // ( 1,-1)
            }
            // sum-of-squares over staged pixels (for channel-L2 norm)
#pragma unroll
            for (int u = 0; u < NSLOT; ++u) {
                if (valid[u]) {
                    u64 v = pl[soff[u]];
                    fma2(ssacc[u], v, v);
                }
            }
        }
        __syncthreads();
    }

    // ---- ssq -> rsqrt in smem (34-stride pixel index == slot index) ----
#pragma unroll
    for (int u = 0; u < NSLOT; ++u)
        if (valid[u]) srn[t + u * NTHREADS] = rsqrtf(sum2(ssacc[u]));
    __syncthreads();

    // ---- apply both norms, write float2 per output channel ----
    const int roff[8] = {-SCOLS, -SCOLS - 1, -1, SCOLS - 1,
                          SCOLS,  SCOLS + 1,  1, -SCOLS + 1};
    float* ob = out + ((size_t)b * 8) * HW + (size_t)(h0 + py) * WW + (w0 + px0);
    const int ci0 = (py + 1) * SCOLS + (px0 + 1);
    const float rc0 = srn[ci0], rc1 = srn[ci0 + 1];
#pragma unroll
    for (int k = 0; k < 8; ++k) {
        float2 v;
        v.x = sum2(acc[0][k]) * rc0 * srn[ci0 + roff[k]];
        v.y = sum2(acc[1][k]) * rc1 * srn[ci0 + 1 + roff[k]];
        *reinterpret_cast<float2*>(ob + (size_t)k * HW) = v;
    }
}

extern "C" void kernel_launch(void* const* d_in, const int* in_sizes, int n_in,
                              void* d_out, int out_size) {
    const float* feats = (const float*)d_in[0];
    float* out = (float*)d_out;
    dim3 grid(WW / TW, HH / TH, 8);
    featcorr_kernel<<<grid, NTHREADS>>>(feats, out);
}